// round 1
// baseline (speedup 1.0000x reference)
#include <cuda_runtime.h>

#define N_NODES 50000
#define N_EDGES 500000
#define HDIM    128
#define H2      256
#define NLAYERS 4
#define NGRAPH  1000
#define MEPS    1e-7f
#define LNEPS   1e-5f

// ---------------- scratch (device globals; no runtime allocation) ----------
__device__ float  g_h[(size_t)N_NODES * HDIM];
__device__ float  g_z[(size_t)N_NODES * HDIM];
__device__ float  g_o[(size_t)N_NODES * HDIM];
__device__ float  g_u[(size_t)N_NODES * H2];
__device__ int    g_cnt[N_NODES + 1];
__device__ int    g_ptr[N_NODES + 1];
__device__ int    g_cur[N_NODES];
__device__ int    g_ssrc[N_EDGES];
__device__ float4 g_sattr[N_EDGES];
__device__ int    g_gcnt[NGRAPH + 1];
__device__ int    g_gptr[NGRAPH + 1];

// ---------------- f32x2 packed FMA helpers ---------------------------------
__device__ __forceinline__ unsigned long long fma2(unsigned long long a,
                                                   unsigned long long b,
                                                   unsigned long long c) {
    unsigned long long d;
    asm("fma.rn.f32x2 %0, %1, %2, %3;" : "=l"(d) : "l"(a), "l"(b), "l"(c));
    return d;
}
__device__ __forceinline__ unsigned long long dup2(float a) {
    unsigned long long d;
    asm("mov.b64 %0, {%1, %1};" : "=l"(d) : "f"(a));
    return d;
}
__device__ __forceinline__ float2 unpack2(unsigned long long v) {
    float2 r;
    asm("mov.b64 {%0, %1}, %2;" : "=f"(r.x), "=f"(r.y) : "l"(v));
    return r;
}

// ---------------- prep kernels ----------------------------------------------
__global__ void k_zero() {
    int i = blockIdx.x * blockDim.x + threadIdx.x;
    if (i <= N_NODES) g_cnt[i] = 0;
    if (i <= NGRAPH) g_gcnt[i] = 0;
}

__global__ void k_hist_dst(const int* __restrict__ ei) {
    int e = blockIdx.x * blockDim.x + threadIdx.x;
    if (e < N_EDGES) atomicAdd(&g_cnt[ei[N_EDGES + e]], 1);
}

__global__ void k_hist_batch(const int* __restrict__ batch) {
    int i = blockIdx.x * blockDim.x + threadIdx.x;
    if (i < N_NODES) atomicAdd(&g_gcnt[batch[i]], 1);
}

// single-block exclusive scan (n <= ~64k); which=0: cnt->ptr, which=1: gcnt->gptr
__global__ void k_scan(int which) {
    const int n = which ? NGRAPH : N_NODES;
    const int* in = which ? g_gcnt : g_cnt;
    int* out = which ? g_gptr : g_ptr;
    __shared__ int buf[1024];
    __shared__ int carry;
    if (threadIdx.x == 0) carry = 0;
    __syncthreads();
    for (int base = 0; base < n; base += 1024) {
        int i = base + threadIdx.x;
        int v = (i < n) ? in[i] : 0;
        buf[threadIdx.x] = v;
        __syncthreads();
        int val = v;
        for (int off = 1; off < 1024; off <<= 1) {
            int t = (threadIdx.x >= off) ? buf[threadIdx.x - off] : 0;
            __syncthreads();
            val += t;
            buf[threadIdx.x] = val;
            __syncthreads();
        }
        if (i < n) out[i] = val - v + carry;
        int total = buf[1023];
        __syncthreads();
        if (threadIdx.x == 0) carry += total;
        __syncthreads();
    }
    if (threadIdx.x == 0) out[n] = carry;
}

__global__ void k_cursor() {
    int i = blockIdx.x * blockDim.x + threadIdx.x;
    if (i < N_NODES) g_cur[i] = g_ptr[i];
}

__global__ void k_scatter(const int* __restrict__ ei, const float* __restrict__ ea) {
    int e = blockIdx.x * blockDim.x + threadIdx.x;
    if (e >= N_EDGES) return;
    int d = ei[N_EDGES + e];
    int pos = atomicAdd(&g_cur[d], 1);
    g_ssrc[pos] = ei[e];
    g_sattr[pos] = make_float4(ea[3 * e], ea[3 * e + 1], ea[3 * e + 2], 0.f);
}

// ---------------- node encoder: h = x @ Wn + bn ------------------------------
__global__ void k_encode(const float* __restrict__ x, const float* __restrict__ W,
                         const float* __restrict__ b) {
    __shared__ float4 sW[9][32];
    __shared__ float4 sb[32];
    int tid = threadIdx.x;
    for (int i = tid; i < 9 * 32; i += blockDim.x)
        sW[i / 32][i % 32] = *(const float4*)&W[(i / 32) * HDIM + (i % 32) * 4];
    if (tid < 32) sb[tid] = *(const float4*)&b[tid * 4];
    __syncthreads();
    int gw = (blockIdx.x * blockDim.x + tid) >> 5;
    if (gw >= N_NODES) return;
    int lane = tid & 31;
    const float* xr = x + gw * 9;
    float xv[9];
#pragma unroll
    for (int k = 0; k < 9; k++) xv[k] = __ldg(&xr[k]);
    float4 acc = sb[lane];
#pragma unroll
    for (int k = 0; k < 9; k++) {
        float4 w = sW[k][lane];
        acc.x += xv[k] * w.x; acc.y += xv[k] * w.y;
        acc.z += xv[k] * w.z; acc.w += xv[k] * w.w;
    }
    ((float4*)g_h)[gw * 32 + lane] = acc;
}

// ---------------- LN(h)*g+b then relu -> g_z ---------------------------------
__global__ void k_lnrelu(const float* __restrict__ g, const float* __restrict__ b) {
    int gw = (blockIdx.x * blockDim.x + threadIdx.x) >> 5;
    if (gw >= N_NODES) return;
    int lane = threadIdx.x & 31;
    float4 v = ((const float4*)g_h)[gw * 32 + lane];
    float s = v.x + v.y + v.z + v.w;
#pragma unroll
    for (int o = 16; o > 0; o >>= 1) s += __shfl_xor_sync(0xffffffffu, s, o);
    float mean = s * (1.f / 128.f);
    float4 d = make_float4(v.x - mean, v.y - mean, v.z - mean, v.w - mean);
    float q = d.x * d.x + d.y * d.y + d.z * d.z + d.w * d.w;
#pragma unroll
    for (int o = 16; o > 0; o >>= 1) q += __shfl_xor_sync(0xffffffffu, q, o);
    float rstd = rsqrtf(q * (1.f / 128.f) + LNEPS);
    float4 gg = __ldg((const float4*)&g[lane * 4]);
    float4 bb = __ldg((const float4*)&b[lane * 4]);
    float4 o4;
    o4.x = fmaxf(d.x * rstd * gg.x + bb.x, 0.f);
    o4.y = fmaxf(d.y * rstd * gg.y + bb.y, 0.f);
    o4.z = fmaxf(d.z * rstd * gg.z + bb.z, 0.f);
    o4.w = fmaxf(d.w * rstd * gg.w + bb.w, 0.f);
    ((float4*)g_z)[gw * 32 + lane] = o4;
}

// ---------------- fused edge softmax-aggregation (warp per node) -------------
// out[n] = sum_e alpha_e * msg_e  + z[n], alpha = softmax(t*msg) over in-edges,
// msg = relu(z[src] + ea) + eps, ea recomputed from 3 attrs (same all layers).
__global__ void __launch_bounds__(256) k_edge(const float* __restrict__ eW,
                                              const float* __restrict__ eb,
                                              const float* __restrict__ tall,
                                              int layer, int use_z) {
    __shared__ float4 sw[4][32];
    int tid = threadIdx.x;
    if (tid < 32) {
        sw[0][tid] = *(const float4*)&eW[0 * HDIM + tid * 4];
        sw[1][tid] = *(const float4*)&eW[1 * HDIM + tid * 4];
        sw[2][tid] = *(const float4*)&eW[2 * HDIM + tid * 4];
        sw[3][tid] = *(const float4*)&eb[tid * 4];
    }
    __syncthreads();
    int gw = (blockIdx.x * blockDim.x + tid) >> 5;
    if (gw >= N_NODES) return;
    int lane = tid & 31;
    const float4* zp = (const float4*)(use_z ? g_z : g_h);
    float tv = __ldg(&tall[layer]);
    int j0 = __ldg(&g_ptr[gw]), j1 = __ldg(&g_ptr[gw + 1]);
    float4 w0 = sw[0][lane], w1 = sw[1][lane], w2 = sw[2][lane], wb = sw[3][lane];
    float4 den = make_float4(0.f, 0.f, 0.f, 0.f);
    float4 num = make_float4(0.f, 0.f, 0.f, 0.f);
    for (int j = j0; j < j1; j++) {
        int s = __ldg(&g_ssrc[j]);
        float4 a = __ldg(&g_sattr[j]);
        float4 hv = __ldg(&zp[s * 32 + lane]);
        float m, e;
        m = fmaxf(hv.x + wb.x + a.x * w0.x + a.y * w1.x + a.z * w2.x, 0.f) + MEPS;
        e = __expf(tv * m); den.x += e; num.x += e * m;
        m = fmaxf(hv.y + wb.y + a.x * w0.y + a.y * w1.y + a.z * w2.y, 0.f) + MEPS;
        e = __expf(tv * m); den.y += e; num.y += e * m;
        m = fmaxf(hv.z + wb.z + a.x * w0.z + a.y * w1.z + a.z * w2.z, 0.f) + MEPS;
        e = __expf(tv * m); den.z += e; num.z += e * m;
        m = fmaxf(hv.w + wb.w + a.x * w0.w + a.y * w1.w + a.z * w2.w, 0.f) + MEPS;
        e = __expf(tv * m); den.w += e; num.w += e * m;
    }
    float4 hz = zp[gw * 32 + lane];
    float4 o;
    if (j1 > j0) {
        o.x = num.x / den.x + hz.x;
        o.y = num.y / den.y + hz.y;
        o.z = num.z / den.z + hz.z;
        o.w = num.w / den.w + hz.w;
    } else {
        o = hz;
    }
    ((float4*)g_o)[gw * 32 + lane] = o;
}

// ---------------- GEMM1: u = relu(LN(g_o @ W1 + b1)) -------------------------
// BM=64, BN=256(full row -> LN fused), BK=8, 256 thr, 8x8/thread, f32x2 FMA.
__global__ void __launch_bounds__(256) k_gemm1(const float* __restrict__ B,
                                               const float* __restrict__ bias,
                                               const float* __restrict__ lg,
                                               const float* __restrict__ lb) {
    __shared__ float As[8][65];
    __shared__ float Bs[8][256];
    const float* A = g_o;
    int tid = threadIdx.x;
    int tx = tid & 31, ty = tid >> 5;
    int row0 = blockIdx.x * 64;
    unsigned long long acc[8][4];
#pragma unroll
    for (int i = 0; i < 8; i++)
#pragma unroll
        for (int j = 0; j < 4; j++) acc[i][j] = 0ull;

    for (int kk = 0; kk < HDIM; kk += 8) {
#pragma unroll
        for (int l = 0; l < 2; l++) {
            int e = tid + l * 256;
            int k = e & 7, m = e >> 3;
            int r = row0 + m;
            As[k][m] = (r < N_NODES) ? A[r * HDIM + kk + k] : 0.f;
        }
#pragma unroll
        for (int l = 0; l < 2; l++) {
            int q = tid + l * 256;
            int k = q >> 6, n4 = q & 63;
            *(float4*)&Bs[k][n4 * 4] = __ldg((const float4*)&B[(kk + k) * H2 + n4 * 4]);
        }
        __syncthreads();
#pragma unroll
        for (int k = 0; k < 8; k++) {
            unsigned long long bv[4];
            bv[0] = *(const unsigned long long*)&Bs[k][tx * 4];
            bv[1] = *(const unsigned long long*)&Bs[k][tx * 4 + 2];
            bv[2] = *(const unsigned long long*)&Bs[k][128 + tx * 4];
            bv[3] = *(const unsigned long long*)&Bs[k][128 + tx * 4 + 2];
#pragma unroll
            for (int i = 0; i < 8; i++) {
                unsigned long long a2 = dup2(As[k][ty * 8 + i]);
#pragma unroll
                for (int j = 0; j < 4; j++) acc[i][j] = fma2(a2, bv[j], acc[i][j]);
            }
        }
        __syncthreads();
    }
    float4 bia0 = __ldg((const float4*)&bias[tx * 4]);
    float4 bia1 = __ldg((const float4*)&bias[128 + tx * 4]);
    float4 gv0 = __ldg((const float4*)&lg[tx * 4]);
    float4 gv1 = __ldg((const float4*)&lg[128 + tx * 4]);
    float4 bv0 = __ldg((const float4*)&lb[tx * 4]);
    float4 bv1 = __ldg((const float4*)&lb[128 + tx * 4]);
#pragma unroll
    for (int i = 0; i < 8; i++) {
        float v[8];
        float2 p;
        p = unpack2(acc[i][0]); v[0] = p.x + bia0.x; v[1] = p.y + bia0.y;
        p = unpack2(acc[i][1]); v[2] = p.x + bia0.z; v[3] = p.y + bia0.w;
        p = unpack2(acc[i][2]); v[4] = p.x + bia1.x; v[5] = p.y + bia1.y;
        p = unpack2(acc[i][3]); v[6] = p.x + bia1.z; v[7] = p.y + bia1.w;
        float s = 0.f;
#pragma unroll
        for (int j = 0; j < 8; j++) s += v[j];
#pragma unroll
        for (int o = 16; o > 0; o >>= 1) s += __shfl_xor_sync(0xffffffffu, s, o);
        float mean = s * (1.f / 256.f);
        float q = 0.f;
#pragma unroll
        for (int j = 0; j < 8; j++) { float d = v[j] - mean; q += d * d; }
#pragma unroll
        for (int o = 16; o > 0; o >>= 1) q += __shfl_xor_sync(0xffffffffu, q, o);
        float rstd = rsqrtf(q * (1.f / 256.f) + LNEPS);
        int r = row0 + ty * 8 + i;
        if (r < N_NODES) {
            float4 o0, o1;
            o0.x = fmaxf((v[0] - mean) * rstd * gv0.x + bv0.x, 0.f);
            o0.y = fmaxf((v[1] - mean) * rstd * gv0.y + bv0.y, 0.f);
            o0.z = fmaxf((v[2] - mean) * rstd * gv0.z + bv0.z, 0.f);
            o0.w = fmaxf((v[3] - mean) * rstd * gv0.w + bv0.w, 0.f);
            o1.x = fmaxf((v[4] - mean) * rstd * gv1.x + bv1.x, 0.f);
            o1.y = fmaxf((v[5] - mean) * rstd * gv1.y + bv1.y, 0.f);
            o1.z = fmaxf((v[6] - mean) * rstd * gv1.z + bv1.z, 0.f);
            o1.w = fmaxf((v[7] - mean) * rstd * gv1.w + bv1.w, 0.f);
            *(float4*)&g_u[(size_t)r * H2 + tx * 4] = o0;
            *(float4*)&g_u[(size_t)r * H2 + 128 + tx * 4] = o1;
        }
    }
}

// ---------------- GEMM2: h (+)= g_u @ W2 + b2 --------------------------------
// BM=128, BN=128, BK=8, 256 thr, 8x8/thread, f32x2 FMA.
__global__ void __launch_bounds__(256) k_gemm2(const float* __restrict__ B,
                                               const float* __restrict__ bias,
                                               int first) {
    __shared__ float As[8][129];
    __shared__ float Bs[8][128];
    const float* A = g_u;
    int tid = threadIdx.x;
    int tx = tid & 15, ty = tid >> 4;
    int row0 = blockIdx.x * 128;
    unsigned long long acc[8][4];
#pragma unroll
    for (int i = 0; i < 8; i++)
#pragma unroll
        for (int j = 0; j < 4; j++) acc[i][j] = 0ull;

    for (int kk = 0; kk < H2; kk += 8) {
        {
            int m = tid >> 1, k0 = (tid & 1) * 4;
            int r = row0 + m;
            float4 av = (r < N_NODES) ? __ldg((const float4*)&A[(size_t)r * H2 + kk + k0])
                                      : make_float4(0.f, 0.f, 0.f, 0.f);
            As[k0 + 0][m] = av.x; As[k0 + 1][m] = av.y;
            As[k0 + 2][m] = av.z; As[k0 + 3][m] = av.w;
        }
        {
            int k = tid >> 5, n4 = tid & 31;
            *(float4*)&Bs[k][n4 * 4] = __ldg((const float4*)&B[(kk + k) * HDIM + n4 * 4]);
        }
        __syncthreads();
#pragma unroll
        for (int k = 0; k < 8; k++) {
            unsigned long long bv[4];
            bv[0] = *(const unsigned long long*)&Bs[k][tx * 4];
            bv[1] = *(const unsigned long long*)&Bs[k][tx * 4 + 2];
            bv[2] = *(const unsigned long long*)&Bs[k][64 + tx * 4];
            bv[3] = *(const unsigned long long*)&Bs[k][64 + tx * 4 + 2];
#pragma unroll
            for (int i = 0; i < 8; i++) {
                unsigned long long a2 = dup2(As[k][ty * 8 + i]);
#pragma unroll
                for (int j = 0; j < 4; j++) acc[i][j] = fma2(a2, bv[j], acc[i][j]);
            }
        }
        __syncthreads();
    }
    float4 bia0 = __ldg((const float4*)&bias[tx * 4]);
    float4 bia1 = __ldg((const float4*)&bias[64 + tx * 4]);
#pragma unroll
    for (int i = 0; i < 8; i++) {
        int r = row0 + ty * 8 + i;
        if (r < N_NODES) {
            float2 p;
            float4 y0, y1;
            p = unpack2(acc[i][0]); y0.x = p.x + bia0.x; y0.y = p.y + bia0.y;
            p = unpack2(acc[i][1]); y0.z = p.x + bia0.z; y0.w = p.y + bia0.w;
            p = unpack2(acc[i][2]); y1.x = p.x + bia1.x; y1.y = p.y + bia1.y;
            p = unpack2(acc[i][3]); y1.z = p.x + bia1.z; y1.w = p.y + bia1.w;
            float* hp = &g_h[(size_t)r * HDIM];
            if (first) {
                *(float4*)&hp[tx * 4] = y0;
                *(float4*)&hp[64 + tx * 4] = y1;
            } else {
                float4 h0 = *(float4*)&hp[tx * 4];
                float4 h1 = *(float4*)&hp[64 + tx * 4];
                h0.x += y0.x; h0.y += y0.y; h0.z += y0.z; h0.w += y0.w;
                h1.x += y1.x; h1.y += y1.y; h1.z += y1.z; h1.w += y1.w;
                *(float4*)&hp[tx * 4] = h0;
                *(float4*)&hp[64 + tx * 4] = h1;
            }
        }
    }
}

// ---------------- global mean pool (deterministic, batch is sorted) ----------
__global__ void k_pool(float* __restrict__ out) {
    int g = blockIdx.x, c = threadIdx.x;
    int s = g_gptr[g], e = g_gptr[g + 1];
    float acc = 0.f;
    for (int i = s; i < e; i++) acc += g_z[(size_t)i * HDIM + c];
    out[g * HDIM + c] = (e > s) ? acc / (float)(e - s) : 0.f;
}

// ---------------- launch ------------------------------------------------------
extern "C" void kernel_launch(void* const* d_in, const int* in_sizes, int n_in,
                              void* d_out, int out_size) {
    (void)in_sizes; (void)n_in; (void)out_size;
    const float* x     = (const float*)d_in[0];
    const int*   ei    = (const int*)d_in[1];
    const float* eattr = (const float*)d_in[2];
    const int*   batch = (const int*)d_in[3];
    const float* encW  = (const float*)d_in[4];
    const float* encb  = (const float*)d_in[5];
    const float* eW    = (const float*)d_in[6];
    const float* eb    = (const float*)d_in[7];
    const float* lng   = (const float*)d_in[8];
    const float* lnb   = (const float*)d_in[9];
    const float* W1    = (const float*)d_in[10];
    const float* b1    = (const float*)d_in[11];
    const float* mg    = (const float*)d_in[12];
    const float* mb    = (const float*)d_in[13];
    const float* W2    = (const float*)d_in[14];
    const float* b2    = (const float*)d_in[15];
    const float* tptr  = (const float*)d_in[16];
    float* out = (float*)d_out;

    const int NWBLK = (N_NODES * 32 + 255) / 256;  // warp-per-node kernels

    // CSR + graph ranges
    k_zero<<<(N_NODES + 256) / 256, 256>>>();
    k_hist_dst<<<(N_EDGES + 255) / 256, 256>>>(ei);
    k_hist_batch<<<(N_NODES + 255) / 256, 256>>>(batch);
    k_scan<<<1, 1024>>>(0);
    k_scan<<<1, 1024>>>(1);
    k_cursor<<<(N_NODES + 255) / 256, 256>>>();
    k_scatter<<<(N_EDGES + 255) / 256, 256>>>(ei, eattr);

    // node encoder
    k_encode<<<NWBLK, 256>>>(x, encW, encb);

    // layers
    for (int i = 0; i < NLAYERS; i++) {
        if (i > 0) k_lnrelu<<<NWBLK, 256>>>(lng + (size_t)i * HDIM, lnb + (size_t)i * HDIM);
        k_edge<<<NWBLK, 256>>>(eW, eb, tptr, i, (i > 0) ? 1 : 0);
        k_gemm1<<<(N_NODES + 63) / 64, 256>>>(W1 + (size_t)i * HDIM * H2,
                                              b1 + (size_t)i * H2,
                                              mg + (size_t)i * H2,
                                              mb + (size_t)i * H2);
        k_gemm2<<<(N_NODES + 127) / 128, 256>>>(W2 + (size_t)i * H2 * HDIM,
                                                b2 + (size_t)i * HDIM,
                                                (i == 0) ? 1 : 0);
    }

    // final norm (layer-0 params) + pool
    k_lnrelu<<<NWBLK, 256>>>(lng, lnb);
    k_pool<<<NGRAPH, HDIM>>>(out);
}

// round 2
// speedup vs baseline: 1.0046x; 1.0046x over previous
#include <cuda_runtime.h>

#define N_NODES 50000
#define N_EDGES 500000
#define HDIM    128
#define H2      256
#define NLAYERS 4
#define NGRAPH  1000
#define MEPS    1e-7f
#define LNEPS   1e-5f

// ---------------- scratch (device globals; no runtime allocation) ----------
__device__ float  g_h[(size_t)N_NODES * HDIM];
__device__ float  g_z[(size_t)N_NODES * HDIM];
__device__ float  g_o[(size_t)N_NODES * HDIM];
__device__ float  g_u[(size_t)N_NODES * H2];
__device__ int    g_cnt[N_NODES + 1];
__device__ int    g_ptr[N_NODES + 1];
__device__ int    g_cur[N_NODES];
__device__ int    g_ssrc[N_EDGES];
__device__ float4 g_sattr[N_EDGES];
__device__ int    g_gcnt[NGRAPH + 1];
__device__ int    g_gptr[NGRAPH + 1];

// ---------------- f32x2 packed FMA helpers ---------------------------------
__device__ __forceinline__ unsigned long long fma2(unsigned long long a,
                                                   unsigned long long b,
                                                   unsigned long long c) {
    unsigned long long d;
    asm("fma.rn.f32x2 %0, %1, %2, %3;" : "=l"(d) : "l"(a), "l"(b), "l"(c));
    return d;
}
__device__ __forceinline__ unsigned long long dup2(float a) {
    unsigned long long d;
    asm("mov.b64 %0, {%1, %1};" : "=l"(d) : "f"(a));
    return d;
}
__device__ __forceinline__ float2 unpack2(unsigned long long v) {
    float2 r;
    asm("mov.b64 {%0, %1}, %2;" : "=f"(r.x), "=f"(r.y) : "l"(v));
    return r;
}

// ---------------- prep kernels ----------------------------------------------
__global__ void k_zero() {
    int i = blockIdx.x * blockDim.x + threadIdx.x;
    if (i <= N_NODES) g_cnt[i] = 0;
    if (i <= NGRAPH) g_gcnt[i] = 0;
}

__global__ void k_hist_dst(const int* __restrict__ ei) {
    int e = blockIdx.x * blockDim.x + threadIdx.x;
    if (e < N_EDGES) atomicAdd(&g_cnt[ei[N_EDGES + e]], 1);
}

__global__ void k_hist_batch(const int* __restrict__ batch) {
    int i = blockIdx.x * blockDim.x + threadIdx.x;
    if (i < N_NODES) atomicAdd(&g_gcnt[batch[i]], 1);
}

// single-block exclusive scan (n <= ~64k); which=0: cnt->ptr, which=1: gcnt->gptr
__global__ void k_scan(int which) {
    const int n = which ? NGRAPH : N_NODES;
    const int* in = which ? g_gcnt : g_cnt;
    int* out = which ? g_gptr : g_ptr;
    __shared__ int buf[1024];
    __shared__ int carry;
    if (threadIdx.x == 0) carry = 0;
    __syncthreads();
    for (int base = 0; base < n; base += 1024) {
        int i = base + threadIdx.x;
        int v = (i < n) ? in[i] : 0;
        buf[threadIdx.x] = v;
        __syncthreads();
        int val = v;
        for (int off = 1; off < 1024; off <<= 1) {
            int t = (threadIdx.x >= off) ? buf[threadIdx.x - off] : 0;
            __syncthreads();
            val += t;
            buf[threadIdx.x] = val;
            __syncthreads();
        }
        if (i < n) out[i] = val - v + carry;
        int total = buf[1023];
        __syncthreads();
        if (threadIdx.x == 0) carry += total;
        __syncthreads();
    }
    if (threadIdx.x == 0) out[n] = carry;
}

__global__ void k_cursor() {
    int i = blockIdx.x * blockDim.x + threadIdx.x;
    if (i < N_NODES) g_cur[i] = g_ptr[i];
}

__global__ void k_scatter(const int* __restrict__ ei, const float* __restrict__ ea) {
    int e = blockIdx.x * blockDim.x + threadIdx.x;
    if (e >= N_EDGES) return;
    int d = ei[N_EDGES + e];
    int pos = atomicAdd(&g_cur[d], 1);
    g_ssrc[pos] = ei[e];
    g_sattr[pos] = make_float4(ea[3 * e], ea[3 * e + 1], ea[3 * e + 2], 0.f);
}

// ---------------- node encoder: h = x @ Wn + bn ------------------------------
__global__ void k_encode(const float* __restrict__ x, const float* __restrict__ W,
                         const float* __restrict__ b) {
    __shared__ float4 sW[9][32];
    __shared__ float4 sb[32];
    int tid = threadIdx.x;
    for (int i = tid; i < 9 * 32; i += blockDim.x)
        sW[i / 32][i % 32] = *(const float4*)&W[(i / 32) * HDIM + (i % 32) * 4];
    if (tid < 32) sb[tid] = *(const float4*)&b[tid * 4];
    __syncthreads();
    int gw = (blockIdx.x * blockDim.x + tid) >> 5;
    if (gw >= N_NODES) return;
    int lane = tid & 31;
    const float* xr = x + gw * 9;
    float xv[9];
#pragma unroll
    for (int k = 0; k < 9; k++) xv[k] = __ldg(&xr[k]);
    float4 acc = sb[lane];
#pragma unroll
    for (int k = 0; k < 9; k++) {
        float4 w = sW[k][lane];
        acc.x += xv[k] * w.x; acc.y += xv[k] * w.y;
        acc.z += xv[k] * w.z; acc.w += xv[k] * w.w;
    }
    ((float4*)g_h)[gw * 32 + lane] = acc;
}

// ---------------- LN(h)*g+b then relu -> g_z ---------------------------------
__global__ void k_lnrelu(const float* __restrict__ g, const float* __restrict__ b) {
    int gw = (blockIdx.x * blockDim.x + threadIdx.x) >> 5;
    if (gw >= N_NODES) return;
    int lane = threadIdx.x & 31;
    float4 v = ((const float4*)g_h)[gw * 32 + lane];
    float s = v.x + v.y + v.z + v.w;
#pragma unroll
    for (int o = 16; o > 0; o >>= 1) s += __shfl_xor_sync(0xffffffffu, s, o);
    float mean = s * (1.f / 128.f);
    float4 d = make_float4(v.x - mean, v.y - mean, v.z - mean, v.w - mean);
    float q = d.x * d.x + d.y * d.y + d.z * d.z + d.w * d.w;
#pragma unroll
    for (int o = 16; o > 0; o >>= 1) q += __shfl_xor_sync(0xffffffffu, q, o);
    float rstd = rsqrtf(q * (1.f / 128.f) + LNEPS);
    float4 gg = __ldg((const float4*)&g[lane * 4]);
    float4 bb = __ldg((const float4*)&b[lane * 4]);
    float4 o4;
    o4.x = fmaxf(d.x * rstd * gg.x + bb.x, 0.f);
    o4.y = fmaxf(d.y * rstd * gg.y + bb.y, 0.f);
    o4.z = fmaxf(d.z * rstd * gg.z + bb.z, 0.f);
    o4.w = fmaxf(d.w * rstd * gg.w + bb.w, 0.f);
    ((float4*)g_z)[gw * 32 + lane] = o4;
}

// ---------------- fused edge softmax-aggregation (warp per node) -------------
// out[n] = sum_e alpha_e * msg_e  + z[n], alpha = softmax(t*msg) over in-edges,
// msg = relu(z[src] + ea) + eps, ea recomputed from 3 attrs (same all layers).
__global__ void __launch_bounds__(256) k_edge(const float* __restrict__ eW,
                                              const float* __restrict__ eb,
                                              const float* __restrict__ tall,
                                              int layer, int use_z) {
    __shared__ float4 sw[4][32];
    int tid = threadIdx.x;
    if (tid < 32) {
        sw[0][tid] = *(const float4*)&eW[0 * HDIM + tid * 4];
        sw[1][tid] = *(const float4*)&eW[1 * HDIM + tid * 4];
        sw[2][tid] = *(const float4*)&eW[2 * HDIM + tid * 4];
        sw[3][tid] = *(const float4*)&eb[tid * 4];
    }
    __syncthreads();
    int gw = (blockIdx.x * blockDim.x + tid) >> 5;
    if (gw >= N_NODES) return;
    int lane = tid & 31;
    const float4* zp = (const float4*)(use_z ? g_z : g_h);
    float tv = __ldg(&tall[layer]);
    int j0 = __ldg(&g_ptr[gw]), j1 = __ldg(&g_ptr[gw + 1]);
    float4 w0 = sw[0][lane], w1 = sw[1][lane], w2 = sw[2][lane], wb = sw[3][lane];
    float4 den = make_float4(0.f, 0.f, 0.f, 0.f);
    float4 num = make_float4(0.f, 0.f, 0.f, 0.f);
    for (int j = j0; j < j1; j++) {
        int s = __ldg(&g_ssrc[j]);
        float4 a = __ldg(&g_sattr[j]);
        float4 hv = __ldg(&zp[s * 32 + lane]);
        float m, e;
        m = fmaxf(hv.x + wb.x + a.x * w0.x + a.y * w1.x + a.z * w2.x, 0.f) + MEPS;
        e = __expf(tv * m); den.x += e; num.x += e * m;
        m = fmaxf(hv.y + wb.y + a.x * w0.y + a.y * w1.y + a.z * w2.y, 0.f) + MEPS;
        e = __expf(tv * m); den.y += e; num.y += e * m;
        m = fmaxf(hv.z + wb.z + a.x * w0.z + a.y * w1.z + a.z * w2.z, 0.f) + MEPS;
        e = __expf(tv * m); den.z += e; num.z += e * m;
        m = fmaxf(hv.w + wb.w + a.x * w0.w + a.y * w1.w + a.z * w2.w, 0.f) + MEPS;
        e = __expf(tv * m); den.w += e; num.w += e * m;
    }
    float4 hz = zp[gw * 32 + lane];
    float4 o;
    if (j1 > j0) {
        o.x = num.x / den.x + hz.x;
        o.y = num.y / den.y + hz.y;
        o.z = num.z / den.z + hz.z;
        o.w = num.w / den.w + hz.w;
    } else {
        o = hz;
    }
    ((float4*)g_o)[gw * 32 + lane] = o;
}

// ---------------- GEMM1: u = relu(LN(g_o @ W1 + b1)) -------------------------
// BM=64, BN=256(full row -> LN fused), BK=8, 256 thr, 8x8/thread, f32x2 FMA.
__global__ void __launch_bounds__(256) k_gemm1(const float* __restrict__ B,
                                               const float* __restrict__ bias,
                                               const float* __restrict__ lg,
                                               const float* __restrict__ lb) {
    __shared__ float As[8][65];
    __shared__ float Bs[8][256];
    const float* A = g_o;
    int tid = threadIdx.x;
    int tx = tid & 31, ty = tid >> 5;
    int row0 = blockIdx.x * 64;
    unsigned long long acc[8][4];
#pragma unroll
    for (int i = 0; i < 8; i++)
#pragma unroll
        for (int j = 0; j < 4; j++) acc[i][j] = 0ull;

    for (int kk = 0; kk < HDIM; kk += 8) {
#pragma unroll
        for (int l = 0; l < 2; l++) {
            int e = tid + l * 256;
            int k = e & 7, m = e >> 3;
            int r = row0 + m;
            As[k][m] = (r < N_NODES) ? A[r * HDIM + kk + k] : 0.f;
        }
#pragma unroll
        for (int l = 0; l < 2; l++) {
            int q = tid + l * 256;
            int k = q >> 6, n4 = q & 63;
            *(float4*)&Bs[k][n4 * 4] = __ldg((const float4*)&B[(kk + k) * H2 + n4 * 4]);
        }
        __syncthreads();
#pragma unroll
        for (int k = 0; k < 8; k++) {
            unsigned long long bv[4];
            bv[0] = *(const unsigned long long*)&Bs[k][tx * 4];
            bv[1] = *(const unsigned long long*)&Bs[k][tx * 4 + 2];
            bv[2] = *(const unsigned long long*)&Bs[k][128 + tx * 4];
            bv[3] = *(const unsigned long long*)&Bs[k][128 + tx * 4 + 2];
#pragma unroll
            for (int i = 0; i < 8; i++) {
                unsigned long long a2 = dup2(As[k][ty * 8 + i]);
#pragma unroll
                for (int j = 0; j < 4; j++) acc[i][j] = fma2(a2, bv[j], acc[i][j]);
            }
        }
        __syncthreads();
    }
    float4 bia0 = __ldg((const float4*)&bias[tx * 4]);
    float4 bia1 = __ldg((const float4*)&bias[128 + tx * 4]);
    float4 gv0 = __ldg((const float4*)&lg[tx * 4]);
    float4 gv1 = __ldg((const float4*)&lg[128 + tx * 4]);
    float4 bv0 = __ldg((const float4*)&lb[tx * 4]);
    float4 bv1 = __ldg((const float4*)&lb[128 + tx * 4]);
#pragma unroll
    for (int i = 0; i < 8; i++) {
        float v[8];
        float2 p;
        p = unpack2(acc[i][0]); v[0] = p.x + bia0.x; v[1] = p.y + bia0.y;
        p = unpack2(acc[i][1]); v[2] = p.x + bia0.z; v[3] = p.y + bia0.w;
        p = unpack2(acc[i][2]); v[4] = p.x + bia1.x; v[5] = p.y + bia1.y;
        p = unpack2(acc[i][3]); v[6] = p.x + bia1.z; v[7] = p.y + bia1.w;
        float s = 0.f;
#pragma unroll
        for (int j = 0; j < 8; j++) s += v[j];
#pragma unroll
        for (int o = 16; o > 0; o >>= 1) s += __shfl_xor_sync(0xffffffffu, s, o);
        float mean = s * (1.f / 256.f);
        float q = 0.f;
#pragma unroll
        for (int j = 0; j < 8; j++) { float d = v[j] - mean; q += d * d; }
#pragma unroll
        for (int o = 16; o > 0; o >>= 1) q += __shfl_xor_sync(0xffffffffu, q, o);
        float rstd = rsqrtf(q * (1.f / 256.f) + LNEPS);
        int r = row0 + ty * 8 + i;
        if (r < N_NODES) {
            float4 o0, o1;
            o0.x = fmaxf((v[0] - mean) * rstd * gv0.x + bv0.x, 0.f);
            o0.y = fmaxf((v[1] - mean) * rstd * gv0.y + bv0.y, 0.f);
            o0.z = fmaxf((v[2] - mean) * rstd * gv0.z + bv0.z, 0.f);
            o0.w = fmaxf((v[3] - mean) * rstd * gv0.w + bv0.w, 0.f);
            o1.x = fmaxf((v[4] - mean) * rstd * gv1.x + bv1.x, 0.f);
            o1.y = fmaxf((v[5] - mean) * rstd * gv1.y + bv1.y, 0.f);
            o1.z = fmaxf((v[6] - mean) * rstd * gv1.z + bv1.z, 0.f);
            o1.w = fmaxf((v[7] - mean) * rstd * gv1.w + bv1.w, 0.f);
            *(float4*)&g_u[(size_t)r * H2 + tx * 4] = o0;
            *(float4*)&g_u[(size_t)r * H2 + 128 + tx * 4] = o1;
        }
    }
}

// ---------------- GEMM2: h (+)= g_u @ W2 + b2 --------------------------------
// BM=128, BN=128, BK=8, 256 thr, 8x8/thread, f32x2 FMA.
__global__ void __launch_bounds__(256) k_gemm2(const float* __restrict__ B,
                                               const float* __restrict__ bias,
                                               int first) {
    __shared__ float As[8][129];
    __shared__ float Bs[8][128];
    const float* A = g_u;
    int tid = threadIdx.x;
    int tx = tid & 15, ty = tid >> 4;
    int row0 = blockIdx.x * 128;
    unsigned long long acc[8][4];
#pragma unroll
    for (int i = 0; i < 8; i++)
#pragma unroll
        for (int j = 0; j < 4; j++) acc[i][j] = 0ull;

    for (int kk = 0; kk < H2; kk += 8) {
        {
            int m = tid >> 1, k0 = (tid & 1) * 4;
            int r = row0 + m;
            float4 av = (r < N_NODES) ? __ldg((const float4*)&A[(size_t)r * H2 + kk + k0])
                                      : make_float4(0.f, 0.f, 0.f, 0.f);
            As[k0 + 0][m] = av.x; As[k0 + 1][m] = av.y;
            As[k0 + 2][m] = av.z; As[k0 + 3][m] = av.w;
        }
        {
            int k = tid >> 5, n4 = tid & 31;
            *(float4*)&Bs[k][n4 * 4] = __ldg((const float4*)&B[(kk + k) * HDIM + n4 * 4]);
        }
        __syncthreads();
#pragma unroll
        for (int k = 0; k < 8; k++) {
            unsigned long long bv[4];
            bv[0] = *(const unsigned long long*)&Bs[k][tx * 4];
            bv[1] = *(const unsigned long long*)&Bs[k][tx * 4 + 2];
            bv[2] = *(const unsigned long long*)&Bs[k][64 + tx * 4];
            bv[3] = *(const unsigned long long*)&Bs[k][64 + tx * 4 + 2];
#pragma unroll
            for (int i = 0; i < 8; i++) {
                unsigned long long a2 = dup2(As[k][ty * 8 + i]);
#pragma unroll
                for (int j = 0; j < 4; j++) acc[i][j] = fma2(a2, bv[j], acc[i][j]);
            }
        }
        __syncthreads();
    }
    float4 bia0 = __ldg((const float4*)&bias[tx * 4]);
    float4 bia1 = __ldg((const float4*)&bias[64 + tx * 4]);
#pragma unroll
    for (int i = 0; i < 8; i++) {
        int r = row0 + ty * 8 + i;
        if (r < N_NODES) {
            float2 p;
            float4 y0, y1;
            p = unpack2(acc[i][0]); y0.x = p.x + bia0.x; y0.y = p.y + bia0.y;
            p = unpack2(acc[i][1]); y0.z = p.x + bia0.z; y0.w = p.y + bia0.w;
            p = unpack2(acc[i][2]); y1.x = p.x + bia1.x; y1.y = p.y + bia1.y;
            p = unpack2(acc[i][3]); y1.z = p.x + bia1.z; y1.w = p.y + bia1.w;
            float* hp = &g_h[(size_t)r * HDIM];
            if (first) {
                *(float4*)&hp[tx * 4] = y0;
                *(float4*)&hp[64 + tx * 4] = y1;
            } else {
                float4 h0 = *(float4*)&hp[tx * 4];
                float4 h1 = *(float4*)&hp[64 + tx * 4];
                h0.x += y0.x; h0.y += y0.y; h0.z += y0.z; h0.w += y0.w;
                h1.x += y1.x; h1.y += y1.y; h1.z += y1.z; h1.w += y1.w;
                *(float4*)&hp[tx * 4] = h0;
                *(float4*)&hp[64 + tx * 4] = h1;
            }
        }
    }
}

// ---------------- global mean pool (deterministic, batch is sorted) ----------
__global__ void k_pool(float* __restrict__ out) {
    int g = blockIdx.x, c = threadIdx.x;
    int s = g_gptr[g], e = g_gptr[g + 1];
    float acc = 0.f;
    for (int i = s; i < e; i++) acc += g_z[(size_t)i * HDIM + c];
    out[g * HDIM + c] = (e > s) ? acc / (float)(e - s) : 0.f;
}

// ---------------- launch ------------------------------------------------------
extern "C" void kernel_launch(void* const* d_in, const int* in_sizes, int n_in,
                              void* d_out, int out_size) {
    (void)in_sizes; (void)n_in; (void)out_size;
    const float* x     = (const float*)d_in[0];
    const int*   ei    = (const int*)d_in[1];
    const float* eattr = (const float*)d_in[2];
    const int*   batch = (const int*)d_in[3];
    const float* encW  = (const float*)d_in[4];
    const float* encb  = (const float*)d_in[5];
    const float* eW    = (const float*)d_in[6];
    const float* eb    = (const float*)d_in[7];
    const float* lng   = (const float*)d_in[8];
    const float* lnb   = (const float*)d_in[9];
    const float* W1    = (const float*)d_in[10];
    const float* b1    = (const float*)d_in[11];
    const float* mg    = (const float*)d_in[12];
    const float* mb    = (const float*)d_in[13];
    const float* W2    = (const float*)d_in[14];
    const float* b2    = (const float*)d_in[15];
    const float* tptr  = (const float*)d_in[16];
    float* out = (float*)d_out;

    const int NWBLK = (N_NODES * 32 + 255) / 256;  // warp-per-node kernels

    // CSR + graph ranges
    k_zero<<<(N_NODES + 256) / 256, 256>>>();
    k_hist_dst<<<(N_EDGES + 255) / 256, 256>>>(ei);
    k_hist_batch<<<(N_NODES + 255) / 256, 256>>>(batch);
    k_scan<<<1, 1024>>>(0);
    k_scan<<<1, 1024>>>(1);
    k_cursor<<<(N_NODES + 255) / 256, 256>>>();
    k_scatter<<<(N_EDGES + 255) / 256, 256>>>(ei, eattr);

    // node encoder
    k_encode<<<NWBLK, 256>>>(x, encW, encb);

    // layers
    for (int i = 0; i < NLAYERS; i++) {
        if (i > 0) k_lnrelu<<<NWBLK, 256>>>(lng + (size_t)i * HDIM, lnb + (size_t)i * HDIM);
        k_edge<<<NWBLK, 256>>>(eW, eb, tptr, i, (i > 0) ? 1 : 0);
        k_gemm1<<<(N_NODES + 63) / 64, 256>>>(W1 + (size_t)i * HDIM * H2,
                                              b1 + (size_t)i * H2,
                                              mg + (size_t)i * H2,
                                              mb + (size_t)i * H2);
        k_gemm2<<<(N_NODES + 127) / 128, 256>>>(W2 + (size_t)i * H2 * HDIM,
                                                b2 + (size_t)i * HDIM,
                                                (i == 0) ? 1 : 0);
    }

    // final norm (layer-0 params) + pool
    k_lnrelu<<<NWBLK, 256>>>(lng, lnb);
    k_pool<<<NGRAPH, HDIM>>>(out);
}